// round 1
// baseline (speedup 1.0000x reference)
#include <cuda_runtime.h>
#include <cstdint>

// SMPL forward kinematics, algebraically reduced:
//   out[b,0]   = 0
//   out[b,c,m] = out[b,par(c),m] + sum_l R[b,par(c)][m][l] * v_c[l]
// where v_c = (off[c,1], off[c,2], off[c,0]) -- the G-permutations cancel.

static __device__ __forceinline__ void cp16(void* smem_dst, const void* gsrc) {
    unsigned s = (unsigned)__cvta_generic_to_shared(smem_dst);
    asm volatile("cp.async.cg.shared.global [%0], [%1], 16;\n" :: "r"(s), "l"(gsrc));
}

// Load matrix jj: floats [9*jj, 9*jj+9) live in float4 entries e0..e0+2 with
// sub-offset r = (9*jj) & 3. All indices compile-time constants.
#define LOADA(e0) do {                                          \
    float4 q0 = my[(e0)]; float4 q1 = my[(e0)+1]; float4 q2 = my[(e0)+2]; \
    A[0]=q0.x; A[1]=q0.y; A[2]=q0.z;  A[3]=q0.w;                \
    A[4]=q1.x; A[5]=q1.y; A[6]=q1.z;  A[7]=q1.w;                \
    A[8]=q2.x; A[9]=q2.y; A[10]=q2.z; A[11]=q2.w;               \
} while(0)

// child c of parent p, matrix rows at A[r + 3m + l]
#define CH(c, p, r, vx, vy, vz) do {                                              \
    px[c] = fmaf(A[(r)+2],(vz), fmaf(A[(r)+1],(vy), fmaf(A[(r)+0],(vx), px[p]))); \
    py[c] = fmaf(A[(r)+5],(vz), fmaf(A[(r)+4],(vy), fmaf(A[(r)+3],(vx), py[p]))); \
    pz[c] = fmaf(A[(r)+8],(vz), fmaf(A[(r)+7],(vy), fmaf(A[(r)+6],(vx), pz[p]))); \
} while(0)

__global__ void __launch_bounds__(128, 1)
smpl_fk_kernel(const float4* __restrict__ in4, float4* __restrict__ out4, int nb) {
    extern __shared__ float4 sm[];
    const int lane = threadIdx.x & 31;
    const int warp = threadIdx.x >> 5;
    float4* wsm = sm + warp * (32 * 55);            // 32 bodies x 55 float4 (padded from 54)

    const long long b0 = ((long long)blockIdx.x * 4 + warp) * 32;

    // ---- Phase 1: coalesced gmem -> smem via cp.async (warp-autonomous) ----
    if (b0 < nb) {
        const float4* src = in4 + b0 * 54;
        const int nbl = (int)min(32LL, (long long)nb - b0);
        #pragma unroll
        for (int bl = 0; bl < 32; bl++) {
            if (bl < nbl) {
                cp16(&wsm[bl * 55 + lane], &src[bl * 54 + lane]);
                int c1 = lane + 32;
                if (c1 < 54) cp16(&wsm[bl * 55 + c1], &src[bl * 54 + c1]);
            }
        }
    }
    asm volatile("cp.async.commit_group;\ncp.async.wait_group 0;\n" ::: "memory");
    __syncwarp();

    const long long b = b0 + lane;
    if (b >= nb) return;

    // ---- Phase 2: per-thread FK from conflict-free smem (stride 55, LDS.128) ----
    const float4* my = wsm + lane * 55;
    float A[12];
    float px[24], py[24], pz[24];
    px[0] = 0.f; py[0] = 0.f; pz[0] = 0.f;

    LOADA(0);                                   // jj=0  (e0=0,  r=0)
    CH(1, 0, 0,  0.0372f, -0.0522f, -0.0112f);
    CH(5, 0, 0, -0.0383f, -0.0575f, -0.0086f);
    CH(9, 0, 0,  0.0028f,  0.0790f, -0.0244f);

    LOADA(2);                                   // jj=1  (e0=2,  r=1)
    CH(2, 1, 1,  0.0276f, -0.2453f,  0.0051f);

    LOADA(4);                                   // jj=2  (e0=4,  r=2)
    CH(3, 2, 2, -0.0094f, -0.2710f, -0.0238f);

    LOADA(6);                                   // jj=3  (e0=6,  r=3)
    CH(4, 3, 3,  0.0261f, -0.0383f,  0.0775f);

    LOADA(11);                                  // jj=5  (e0=11, r=1)
    CH(6, 5, 1, -0.0275f, -0.2436f, -0.0031f);

    LOADA(13);                                  // jj=6  (e0=13, r=2)
    CH(7, 6, 2,  0.0121f, -0.2666f, -0.0219f);

    LOADA(15);                                  // jj=7  (e0=15, r=3)
    CH(8, 7, 3, -0.0221f, -0.0394f,  0.0827f);

    LOADA(20);                                  // jj=9  (e0=20, r=1)
    CH(10, 9, 1,  0.0028f,  0.0876f,  0.0170f);

    LOADA(22);                                  // jj=10 (e0=22, r=2)
    CH(11, 10, 2, -0.0014f,  0.0356f,  0.0018f);

    LOADA(24);                                  // jj=11 (e0=24, r=3)
    CH(12, 11, 3, -0.0085f,  0.1343f, -0.0212f);
    CH(14, 11, 3,  0.0455f,  0.0724f, -0.0120f);
    CH(19, 11, 3, -0.0527f,  0.0714f, -0.0150f);

    LOADA(27);                                  // jj=12 (e0=27, r=0)
    CH(13, 12, 0,  0.0064f,  0.0565f,  0.0320f);

    LOADA(31);                                  // jj=14 (e0=31, r=2)
    CH(15, 14, 2,  0.0780f,  0.0287f, -0.0121f);

    LOADA(33);                                  // jj=15 (e0=33, r=3)
    CH(16, 15, 3,  0.1621f, -0.0099f, -0.0146f);

    LOADA(36);                                  // jj=16 (e0=36, r=0)
    CH(17, 16, 0,  0.1687f,  0.0081f, -0.0047f);

    LOADA(38);                                  // jj=17 (e0=38, r=1)
    CH(18, 17, 1,  0.0550f, -0.0068f, -0.0099f);

    LOADA(42);                                  // jj=19 (e0=42, r=3)
    CH(20, 19, 3, -0.0719f,  0.0297f, -0.0054f);

    LOADA(45);                                  // jj=20 (e0=45, r=0)
    CH(21, 20, 0, -0.1651f, -0.0091f, -0.0198f);

    LOADA(47);                                  // jj=21 (e0=47, r=1)
    CH(22, 21, 1, -0.1708f,  0.0043f, -0.0038f);

    LOADA(49);                                  // jj=22 (e0=49, r=2)
    CH(23, 22, 2, -0.0563f, -0.0055f, -0.0064f);

    // ---- Phase 3: pack 24x3 floats into 18 float4 stores ----
    float of[72];
    #pragma unroll
    for (int j = 0; j < 24; j++) {
        of[3*j + 0] = px[j];
        of[3*j + 1] = py[j];
        of[3*j + 2] = pz[j];
    }
    float4* dst = out4 + b * 18;
    #pragma unroll
    for (int k = 0; k < 18; k++)
        dst[k] = make_float4(of[4*k], of[4*k+1], of[4*k+2], of[4*k+3]);
}

extern "C" void kernel_launch(void* const* d_in, const int* in_sizes, int n_in,
                              void* d_out, int out_size) {
    const float4* in4 = (const float4*)d_in[0];   // orientations [B,24,3,3] f32
    float4* out4 = (float4*)d_out;                // [B,24,3] f32
    const int nb = in_sizes[0] / 216;             // B
    const int smem = 32 * 55 * 16 * 4;            // 112,640 B
    cudaFuncSetAttribute(smpl_fk_kernel, cudaFuncAttributeMaxDynamicSharedMemorySize, smem);
    const int blocks = (nb + 127) / 128;
    smpl_fk_kernel<<<blocks, 128, smem>>>(in4, out4, nb);
}

// round 2
// speedup vs baseline: 1.1054x; 1.1054x over previous
#include <cuda_runtime.h>
#include <cstdint>

// SMPL forward kinematics, algebraically reduced:
//   out[b,0]   = 0
//   out[b,c,m] = out[b,par(c),m] + sum_l R[b,par(c)][m][l] * v_c[l]
// where v_c = (off[c,1], off[c,2], off[c,0]) -- the G-permutations cancel.
//
// Layout: warp-autonomous 32-body tiles. Input staged in smem at stride 55
// float4/body (odd -> conflict-free LDS.128). Output staged back into the
// same smem at stride 19 float4/body, then streamed out fully coalesced.
// Dead leaf-joint matrix entries {9,10,18,19,52,53} are never loaded
// (entries 18/19 and 52/53 are whole DRAM sectors -> real traffic saved).

static __device__ __forceinline__ void cp16(void* smem_dst, const void* gsrc) {
    unsigned s = (unsigned)__cvta_generic_to_shared(smem_dst);
    asm volatile("cp.async.cg.shared.global [%0], [%1], 16;\n" :: "r"(s), "l"(gsrc));
}

#define LOADA(e0) do {                                          \
    float4 q0 = my[(e0)]; float4 q1 = my[(e0)+1]; float4 q2 = my[(e0)+2]; \
    A[0]=q0.x; A[1]=q0.y; A[2]=q0.z;  A[3]=q0.w;                \
    A[4]=q1.x; A[5]=q1.y; A[6]=q1.z;  A[7]=q1.w;                \
    A[8]=q2.x; A[9]=q2.y; A[10]=q2.z; A[11]=q2.w;               \
} while(0)

#define CH(c, p, r, vx, vy, vz) do {                                              \
    px[c] = fmaf(A[(r)+2],(vz), fmaf(A[(r)+1],(vy), fmaf(A[(r)+0],(vx), px[p]))); \
    py[c] = fmaf(A[(r)+5],(vz), fmaf(A[(r)+4],(vy), fmaf(A[(r)+3],(vx), py[p]))); \
    pz[c] = fmaf(A[(r)+8],(vz), fmaf(A[(r)+7],(vy), fmaf(A[(r)+6],(vx), pz[p]))); \
} while(0)

__global__ void __launch_bounds__(128, 1)
smpl_fk_kernel(const float4* __restrict__ in4, float4* __restrict__ out4, int nb) {
    extern __shared__ float4 sm[];
    const int lane = threadIdx.x & 31;
    const int warp = threadIdx.x >> 5;
    float4* wsm = sm + warp * (32 * 55);            // 32 bodies x 55 float4 (padded from 54)

    const long long b0 = ((long long)blockIdx.x * 4 + warp) * 32;
    const int nbl = (b0 >= nb) ? 0 : (int)min(32LL, (long long)nb - b0);

    // Entry usage: entries {9,10,18,19,52,53} are dead (leaf-joint matrices).
    const bool do1 = !(lane == 9 || lane == 10 || lane == 18 || lane == 19);
    const bool do2 = (lane < 20);                   // lane+32 in [32,51]

    // ---- Phase 1: coalesced gmem -> smem via cp.async (warp-autonomous) ----
    if (nbl == 32) {
        const float4* src = in4 + b0 * 54;
        #pragma unroll
        for (int bl = 0; bl < 32; bl++) {
            if (do1) cp16(&wsm[bl * 55 + lane],      &src[bl * 54 + lane]);
            if (do2) cp16(&wsm[bl * 55 + lane + 32], &src[bl * 54 + lane + 32]);
        }
    } else if (nbl > 0) {
        const float4* src = in4 + b0 * 54;
        for (int bl = 0; bl < nbl; bl++) {
            if (do1) cp16(&wsm[bl * 55 + lane],      &src[bl * 54 + lane]);
            if (do2) cp16(&wsm[bl * 55 + lane + 32], &src[bl * 54 + lane + 32]);
        }
    }
    asm volatile("cp.async.commit_group;\ncp.async.wait_group 0;\n" ::: "memory");
    __syncwarp();
    if (nbl == 0) return;

    // ---- Phase 2: per-thread FK from conflict-free smem (stride 55, LDS.128) ----
    const float4* my = wsm + lane * 55;
    float A[12];
    float px[24], py[24], pz[24];
    px[0] = 0.f; py[0] = 0.f; pz[0] = 0.f;

    LOADA(0);                                   // j=0  (r=0)
    CH(1, 0, 0,  0.0372f, -0.0522f, -0.0112f);
    CH(5, 0, 0, -0.0383f, -0.0575f, -0.0086f);
    CH(9, 0, 0,  0.0028f,  0.0790f, -0.0244f);

    LOADA(2);                                   // j=1  (r=1)
    CH(2, 1, 1,  0.0276f, -0.2453f,  0.0051f);

    LOADA(4);                                   // j=2  (r=2)
    CH(3, 2, 2, -0.0094f, -0.2710f, -0.0238f);

    LOADA(6);                                   // j=3  (r=3)
    CH(4, 3, 3,  0.0261f, -0.0383f,  0.0775f);

    LOADA(11);                                  // j=5  (r=1)
    CH(6, 5, 1, -0.0275f, -0.2436f, -0.0031f);

    LOADA(13);                                  // j=6  (r=2)
    CH(7, 6, 2,  0.0121f, -0.2666f, -0.0219f);

    LOADA(15);                                  // j=7  (r=3)
    CH(8, 7, 3, -0.0221f, -0.0394f,  0.0827f);

    LOADA(20);                                  // j=9  (r=1)
    CH(10, 9, 1,  0.0028f,  0.0876f,  0.0170f);

    LOADA(22);                                  // j=10 (r=2)
    CH(11, 10, 2, -0.0014f,  0.0356f,  0.0018f);

    LOADA(24);                                  // j=11 (r=3)
    CH(12, 11, 3, -0.0085f,  0.1343f, -0.0212f);
    CH(14, 11, 3,  0.0455f,  0.0724f, -0.0120f);
    CH(19, 11, 3, -0.0527f,  0.0714f, -0.0150f);

    LOADA(27);                                  // j=12 (r=0)
    CH(13, 12, 0,  0.0064f,  0.0565f,  0.0320f);

    LOADA(31);                                  // j=14 (r=2)
    CH(15, 14, 2,  0.0780f,  0.0287f, -0.0121f);

    LOADA(33);                                  // j=15 (r=3)
    CH(16, 15, 3,  0.1621f, -0.0099f, -0.0146f);

    LOADA(36);                                  // j=16 (r=0)
    CH(17, 16, 0,  0.1687f,  0.0081f, -0.0047f);

    LOADA(38);                                  // j=17 (r=1)
    CH(18, 17, 1,  0.0550f, -0.0068f, -0.0099f);

    LOADA(42);                                  // j=19 (r=3)
    CH(20, 19, 3, -0.0719f,  0.0297f, -0.0054f);

    LOADA(45);                                  // j=20 (r=0)
    CH(21, 20, 0, -0.1651f, -0.0091f, -0.0198f);

    LOADA(47);                                  // j=21 (r=1)
    CH(22, 21, 1, -0.1708f,  0.0043f, -0.0038f);

    LOADA(49);                                  // j=22 (r=2)
    CH(23, 22, 2, -0.0563f, -0.0055f, -0.0064f);

    // ---- Phase 3: stage outputs to smem (stride 19 -> conflict-free), then
    //      stream out fully coalesced. Reuses the input tile buffer. ----
    float of[72];
    #pragma unroll
    for (int j = 0; j < 24; j++) {
        of[3*j + 0] = px[j];
        of[3*j + 1] = py[j];
        of[3*j + 2] = pz[j];
    }

    __syncwarp();          // all lanes done reading their input columns
    float4* som = wsm;     // 32 bodies x 19 float4 (only 18 used)
    #pragma unroll
    for (int k = 0; k < 18; k++)
        som[lane * 19 + k] = make_float4(of[4*k], of[4*k+1], of[4*k+2], of[4*k+3]);
    __syncwarp();

    float4* dstw = out4 + b0 * 18;              // warp-contiguous output region
    const int lim = nbl * 18;
    #pragma unroll
    for (int k = 0; k < 18; k++) {
        int idx = k * 32 + lane;                // 0 .. 575, contiguous across warp
        int bl  = idx / 18;
        int e   = idx - bl * 18;
        if (idx < lim) dstw[idx] = som[bl * 19 + e];
    }
}

extern "C" void kernel_launch(void* const* d_in, const int* in_sizes, int n_in,
                              void* d_out, int out_size) {
    const float4* in4 = (const float4*)d_in[0];   // orientations [B,24,3,3] f32
    float4* out4 = (float4*)d_out;                // [B,24,3] f32
    const int nb = in_sizes[0] / 216;             // B
    const int smem = 32 * 55 * 16 * 4;            // 112,640 B
    cudaFuncSetAttribute(smpl_fk_kernel, cudaFuncAttributeMaxDynamicSharedMemorySize, smem);
    const int blocks = (nb + 127) / 128;
    smpl_fk_kernel<<<blocks, 128, smem>>>(in4, out4, nb);
}

// round 3
// speedup vs baseline: 1.1405x; 1.0318x over previous
#include <cuda_runtime.h>
#include <cstdint>

// SMPL forward kinematics, algebraically reduced:
//   out[b,0]   = 0
//   out[b,c,m] = out[b,par(c),m] + sum_l R[b,par(c)][m][l] * v_c[l]
// where v_c = (off[c,1], off[c,2], off[c,0]) -- the G-permutations cancel.
//
// R3: persistent warps, 16-body tiles, DOUBLE-BUFFERED cp.async pipeline
// (prefetch tile t+1 while computing tile t) so the per-warp DRAM request
// stream never drains. Input staged at stride 55 float4/body (odd ->
// conflict-free LDS.128); output staged at stride 19 then streamed out
// fully coalesced. Dead leaf-matrix entries {9,10,18,19,52,53} skipped.

#define TB 16                       // bodies per tile
#define STRIDE 55                   // float4 per body in smem
#define BUFQ (TB * STRIDE)          // 880 float4 per buffer

static __device__ __forceinline__ void cp16(void* smem_dst, const void* gsrc) {
    unsigned s = (unsigned)__cvta_generic_to_shared(smem_dst);
    asm volatile("cp.async.cg.shared.global [%0], [%1], 16;\n" :: "r"(s), "l"(gsrc));
}

#define LOADA(e0) do {                                          \
    float4 q0 = my[(e0)]; float4 q1 = my[(e0)+1]; float4 q2 = my[(e0)+2]; \
    A[0]=q0.x; A[1]=q0.y; A[2]=q0.z;  A[3]=q0.w;                \
    A[4]=q1.x; A[5]=q1.y; A[6]=q1.z;  A[7]=q1.w;                \
    A[8]=q2.x; A[9]=q2.y; A[10]=q2.z; A[11]=q2.w;               \
} while(0)

#define CH(c, p, r, vx, vy, vz) do {                                              \
    px[c] = fmaf(A[(r)+2],(vz), fmaf(A[(r)+1],(vy), fmaf(A[(r)+0],(vx), px[p]))); \
    py[c] = fmaf(A[(r)+5],(vz), fmaf(A[(r)+4],(vy), fmaf(A[(r)+3],(vx), py[p]))); \
    pz[c] = fmaf(A[(r)+8],(vz), fmaf(A[(r)+7],(vy), fmaf(A[(r)+6],(vx), pz[p]))); \
} while(0)

__global__ void __launch_bounds__(128, 2)
smpl_fk_kernel(const float4* __restrict__ in4, float4* __restrict__ out4, int nb) {
    extern __shared__ float4 sm[];
    const int lane = threadIdx.x & 31;
    const int warp = threadIdx.x >> 5;
    float4* const buf0 = sm + warp * (2 * BUFQ);
    float4* const buf1 = buf0 + BUFQ;

    const int nT = (nb + TB - 1) / TB;
    const int wstride = gridDim.x * 4;
    int t = blockIdx.x * 4 + warp;
    if (t >= nT) return;

    // Dead entries {9,10,18,19,52,53} (leaf-joint matrices) never loaded.
    const bool do1 = !(lane == 9 || lane == 10 || lane == 18 || lane == 19);
    const bool do2 = (lane < 20);

    // ---- issue one tile's loads + commit as a group ----
    auto load_tile = [&](int tt, float4* buf) {
        const long long b0 = (long long)tt * TB;
        const float4* src = in4 + b0 * 54;
        const int nbl = (int)min((long long)TB, (long long)nb - b0);
        if (nbl == TB) {
            #pragma unroll
            for (int bl = 0; bl < TB; bl++) {
                if (do1) cp16(&buf[bl*STRIDE + lane],      &src[bl*54 + lane]);
                if (do2) cp16(&buf[bl*STRIDE + lane + 32], &src[bl*54 + lane + 32]);
            }
        } else {
            for (int bl = 0; bl < nbl; bl++) {
                if (do1) cp16(&buf[bl*STRIDE + lane],      &src[bl*54 + lane]);
                if (do2) cp16(&buf[bl*STRIDE + lane + 32], &src[bl*54 + lane + 32]);
            }
        }
        asm volatile("cp.async.commit_group;\n" ::: "memory");
    };

    load_tile(t, buf0);                    // prologue
    int cur = 0;

    while (true) {
        const int tn = t + wstride;
        float4* const cbuf = cur ? buf1 : buf0;
        if (tn < nT) {
            load_tile(tn, cur ? buf0 : buf1);                    // prefetch
            asm volatile("cp.async.wait_group 1;\n" ::: "memory");
        } else {
            asm volatile("cp.async.wait_group 0;\n" ::: "memory");
        }
        __syncwarp();

        // ---- compute tile t from cbuf ----
        const long long b0 = (long long)t * TB;
        const int nbl = (int)min((long long)TB, (long long)nb - b0);
        float of[72];
        const bool active = (lane < nbl);
        if (active) {
            const float4* my = cbuf + lane * STRIDE;
            float A[12];
            float px[24], py[24], pz[24];
            px[0] = 0.f; py[0] = 0.f; pz[0] = 0.f;

            LOADA(0);                                   // j=0  (r=0)
            CH(1, 0, 0,  0.0372f, -0.0522f, -0.0112f);
            CH(5, 0, 0, -0.0383f, -0.0575f, -0.0086f);
            CH(9, 0, 0,  0.0028f,  0.0790f, -0.0244f);
            LOADA(2);                                   // j=1  (r=1)
            CH(2, 1, 1,  0.0276f, -0.2453f,  0.0051f);
            LOADA(4);                                   // j=2  (r=2)
            CH(3, 2, 2, -0.0094f, -0.2710f, -0.0238f);
            LOADA(6);                                   // j=3  (r=3)
            CH(4, 3, 3,  0.0261f, -0.0383f,  0.0775f);
            LOADA(11);                                  // j=5  (r=1)
            CH(6, 5, 1, -0.0275f, -0.2436f, -0.0031f);
            LOADA(13);                                  // j=6  (r=2)
            CH(7, 6, 2,  0.0121f, -0.2666f, -0.0219f);
            LOADA(15);                                  // j=7  (r=3)
            CH(8, 7, 3, -0.0221f, -0.0394f,  0.0827f);
            LOADA(20);                                  // j=9  (r=1)
            CH(10, 9, 1,  0.0028f,  0.0876f,  0.0170f);
            LOADA(22);                                  // j=10 (r=2)
            CH(11, 10, 2, -0.0014f,  0.0356f,  0.0018f);
            LOADA(24);                                  // j=11 (r=3)
            CH(12, 11, 3, -0.0085f,  0.1343f, -0.0212f);
            CH(14, 11, 3,  0.0455f,  0.0724f, -0.0120f);
            CH(19, 11, 3, -0.0527f,  0.0714f, -0.0150f);
            LOADA(27);                                  // j=12 (r=0)
            CH(13, 12, 0,  0.0064f,  0.0565f,  0.0320f);
            LOADA(31);                                  // j=14 (r=2)
            CH(15, 14, 2,  0.0780f,  0.0287f, -0.0121f);
            LOADA(33);                                  // j=15 (r=3)
            CH(16, 15, 3,  0.1621f, -0.0099f, -0.0146f);
            LOADA(36);                                  // j=16 (r=0)
            CH(17, 16, 0,  0.1687f,  0.0081f, -0.0047f);
            LOADA(38);                                  // j=17 (r=1)
            CH(18, 17, 1,  0.0550f, -0.0068f, -0.0099f);
            LOADA(42);                                  // j=19 (r=3)
            CH(20, 19, 3, -0.0719f,  0.0297f, -0.0054f);
            LOADA(45);                                  // j=20 (r=0)
            CH(21, 20, 0, -0.1651f, -0.0091f, -0.0198f);
            LOADA(47);                                  // j=21 (r=1)
            CH(22, 21, 1, -0.1708f,  0.0043f, -0.0038f);
            LOADA(49);                                  // j=22 (r=2)
            CH(23, 22, 2, -0.0563f, -0.0055f, -0.0064f);

            #pragma unroll
            for (int j = 0; j < 24; j++) {
                of[3*j + 0] = px[j];
                of[3*j + 1] = py[j];
                of[3*j + 2] = pz[j];
            }
        }

        __syncwarp();                       // all compute reads of cbuf done
        if (active) {                       // stage at stride 19 (conflict-free)
            #pragma unroll
            for (int k = 0; k < 18; k++)
                cbuf[lane * 19 + k] = make_float4(of[4*k], of[4*k+1], of[4*k+2], of[4*k+3]);
        }
        __syncwarp();

        // ---- fully coalesced store stream: nbl*18 contiguous float4 ----
        float4* dstw = out4 + b0 * 18;
        const int lim = nbl * 18;           // <= 288
        #pragma unroll
        for (int k = 0; k < 9; k++) {
            int idx = k * 32 + lane;
            int bl  = idx / 18;
            int e   = idx - bl * 18;
            if (idx < lim) dstw[idx] = cbuf[bl * 19 + e];
        }
        __syncwarp();                       // stream reads done before cbuf reused

        if (tn >= nT) break;
        t = tn;
        cur ^= 1;
    }
}

extern "C" void kernel_launch(void* const* d_in, const int* in_sizes, int n_in,
                              void* d_out, int out_size) {
    const float4* in4 = (const float4*)d_in[0];   // orientations [B,24,3,3] f32
    float4* out4 = (float4*)d_out;                // [B,24,3] f32
    const int nb = in_sizes[0] / 216;             // B
    const int smem = 4 * 2 * BUFQ * 16;           // 112,640 B
    cudaFuncSetAttribute(smpl_fk_kernel, cudaFuncAttributeMaxDynamicSharedMemorySize, smem);
    const int nT = (nb + TB - 1) / TB;
    int blocks = 296;                              // 2 per SM (148 SMs)
    const int maxb = (nT + 3) / 4;
    if (blocks > maxb) blocks = maxb;
    if (blocks < 1) blocks = 1;
    smpl_fk_kernel<<<blocks, 128, smem>>>(in4, out4, nb);
}